// round 13
// baseline (speedup 1.0000x reference)
#include <cuda_runtime.h>

// 2-layer LSTM (H=50), T=65536 serial steps, one persistent CTA, 256 threads.
// R12 skeleton (shuffle-quad, overlapping 8-warp unit coverage, ypart
// y-reduction, 2 barriers) with ALL vector operands loaded directly as
// ulonglong2 (packed f32x2 pairs) so fma.rn.f32x2 consumes load destination
// registers with zero packing MOVs (the pk2 inline-asm movs in R12 were
// suspected dead weight ~80-100 instrs/thread/step).

#define HDIM     50
#define INP      8
#define CHUNK    1024
#define NTHREADS 256

typedef unsigned long long u64;

__device__ __forceinline__ u64 pk2(float lo, float hi) {
    u64 r; asm("mov.b64 %0, {%1,%2};" : "=l"(r) : "f"(lo), "f"(hi)); return r;
}
__device__ __forceinline__ float2 upk2(u64 v) {
    float2 f; asm("mov.b64 {%0,%1}, %2;" : "=f"(f.x), "=f"(f.y) : "l"(v)); return f;
}
__device__ __forceinline__ u64 ffma2(u64 a, u64 b, u64 c) {
    u64 d; asm("fma.rn.f32x2 %0, %1, %2, %3;" : "=l"(d) : "l"(a), "l"(b), "l"(c)); return d;
}
__device__ __forceinline__ u64 add2(u64 a, u64 b) {
    u64 d; asm("add.rn.f32x2 %0, %1, %2;" : "=l"(d) : "l"(a), "l"(b)); return d;
}
__device__ __forceinline__ float tanha(float x) {
    float r; asm("tanh.approx.f32 %0, %1;" : "=f"(r) : "f"(x)); return r;
}

__global__ __launch_bounds__(NTHREADS, 1)
void lstm_r13_kernel(const float* __restrict__ input_seq,
                     const float* __restrict__ W_ih1, const float* __restrict__ W_hh1,
                     const float* __restrict__ b_ih1, const float* __restrict__ b_hh1,
                     const float* __restrict__ W_ih2, const float* __restrict__ W_hh2,
                     const float* __restrict__ b_ih2, const float* __restrict__ b_hh2,
                     const float* __restrict__ W_out, const float* __restrict__ b_out,
                     float* __restrict__ out, int T)
{
    __shared__ __align__(16) float sh1[52];    // h1(s), [50..51]=0
    __shared__ __align__(16) float sh2[52];    // h2(s), [50..51]=0
    __shared__ __align__(16) float ypart[8];   // per-warp wout.h2 partials
    __shared__ __align__(16) float xbuf[(CHUNK + 1) * INP];

    const int t = threadIdx.x;
    const int w = t >> 5;
    const int l = t & 31;
    const int k = l >> 3;                 // gate kind: 0=i 1=f 2=g 3=o
    const int j0 = l & 7;                 // unit-within-warp
    const int u = 6 * w + j0;             // unit 0..49 (overlapping coverage)
    const bool writer = (j0 < 6) || (w == 7);   // unique owner of unit u
    const int row = k * HDIM + u;

    // activation: act(x) = fmaf(tanha(K*x), K, A); K folded into the weights
    const float actK = (k == 2) ? 1.0f : 0.5f;
    const float actA = (k == 2) ? 0.0f : 0.5f;

    // ---- per-thread full-row weights, pre-scaled by actK (f32x2; [25]=pad)
    u64 wx[3], wh1[26], wi2[26], wh2[26];
    float w6K, w7K, bb1K, bb2K;
    {
        const float* r1 = W_ih1 + row * INP;
        wx[0] = pk2(actK * r1[0], actK * r1[1]);
        wx[1] = pk2(actK * r1[2], actK * r1[3]);
        wx[2] = pk2(actK * r1[4], actK * r1[5]);
        w6K = actK * r1[6]; w7K = actK * r1[7];
        const float* r2 = W_hh1 + row * HDIM;
        const float* r3 = W_ih2 + row * HDIM;
        const float* r4 = W_hh2 + row * HDIM;
        #pragma unroll
        for (int j = 0; j < 25; ++j) {
            wh1[j] = pk2(actK * r2[2*j], actK * r2[2*j+1]);
            wi2[j] = pk2(actK * r3[2*j], actK * r3[2*j+1]);
            wh2[j] = pk2(actK * r4[2*j], actK * r4[2*j+1]);
        }
        wh1[25] = 0ULL; wi2[25] = 0ULL; wh2[25] = 0ULL;
        bb1K = actK * (b_ih1[row] + b_hh1[row]);
        bb2K = actK * (b_ih2[row] + b_hh2[row]);
    }
    const float bo = b_out[0];
    const float wout_u = (k == 0 && writer) ? W_out[u] : 0.0f;
    if (t < 52) { sh1[t] = 0.0f; sh2[t] = 0.0f; }
    if (t < 8)  ypart[t] = 0.0f;

    // loop-invariant packed constants
    const u64 bb1Kp = pk2(bb1K, 0.0f);
    const u64 bb2Kp = pk2(bb2K, 0.0f);
    const u64 zer2  = pk2(0.0f, 0.0f);

    float c1 = 0.0f, c2 = 0.0f, err = 0.0f, a1p = 0.0f;
    float x7_use = 0.0f, x7_next = 0.0f;
    __syncthreads();

    #pragma unroll 1
    for (int s = 0; s < T; ++s) {
        const int lo = s & (CHUNK - 1);
        if (lo == 0) {
            // old xbuf fully consumed at BAR_B of step s-1
            const float4* src = (const float4*)(input_seq + (size_t)s * INP);
            float4* dst = (float4*)xbuf;
            int n4 = (CHUNK + 1) * 2;
            int rem4 = (T - s) * 2;
            if (rem4 < n4) n4 = rem4;
            for (int i = t; i < n4; i += NTHREADS) dst[i] = src[i];
            __syncthreads();
            if (s == 0) {
                // bootstrap a1p(0); x7_next = x(0)[7]
                const ulonglong2* xv = (const ulonglong2*)xbuf;
                ulonglong2 x01 = xv[0], x45 = xv[1];
                float2 x67 = upk2(x45.y);
                u64 a0 = ffma2(wx[0], x01.x, bb1Kp);
                u64 a1 = ffma2(wx[1], x01.y, pk2(w6K * x67.x, 0.0f));
                a0 = ffma2(wx[2], x45.x, a0);
                float2 f = upk2(add2(a0, a1));
                a1p = f.x + f.y;
                x7_next = x67.y;
            }
        }

        // ================= Phase A =================
        // x(s+1) loads (u64 direct) + W_ih1@x FMAs (carried into Phase B)
        const ulonglong2* xv = (const ulonglong2*)(&xbuf[(lo + 1) * INP]);
        ulonglong2 x01 = xv[0], x45 = xv[1];
        float2 x67 = upk2(x45.y);
        u64 a0 = ffma2(wx[0], x01.x, bb1Kp);
        u64 a1 = ffma2(wx[1], x01.y, pk2(w6K * x67.x, 0.0f));
        a0 = ffma2(wx[2], x45.x, a0);

        // y(s-1) from per-warp partials (u64 loads, packed adds)
        {
            const ulonglong2* yv = (const ulonglong2*)ypart;
            ulonglong2 ya = yv[0], yb = yv[1];
            float2 yf = upk2(add2(add2(ya.x, ya.y), add2(yb.x, yb.y)));
            float y = bo + (yf.x + yf.y);
            err = (s != 0) ? fmaf(0.1f, x7_use - y, 0.9f * err) : 0.0f;
            if (t == 0 && s != 0) out[s - 1] = y;
        }

        // W_hh2 @ h2(s-1), 4 ILP chains, operands straight from LDS.128
        u64 q0 = bb2Kp, q1 = zer2, q2 = zer2, q3 = zer2;
        {
            const ulonglong2* hv = (const ulonglong2*)sh2;
            #pragma unroll
            for (int j = 0; j < 6; ++j) {
                ulonglong2 ha = hv[2*j];
                ulonglong2 hb = hv[2*j + 1];
                q0 = ffma2(wh2[4*j],     ha.x, q0);
                q1 = ffma2(wh2[4*j + 1], ha.y, q1);
                q2 = ffma2(wh2[4*j + 2], hb.x, q2);
                q3 = ffma2(wh2[4*j + 3], hb.y, q3);
            }
            ulonglong2 hc = hv[12];
            q0 = ffma2(wh2[24], hc.x, q0);
            q1 = ffma2(wh2[25], hc.y, q1);
        }
        // gates1 finish + activation + quad shuffle + cell1
        {
            float g1K = fmaf(w7K, err, a1p);
            float v0 = fmaf(tanha(g1K), actK, actA);
            float I = __shfl_sync(0xffffffffu, v0, j0);
            float F = __shfl_sync(0xffffffffu, v0, j0 + 8);
            float G = __shfl_sync(0xffffffffu, v0, j0 + 16);
            float O = __shfl_sync(0xffffffffu, v0, j0 + 24);
            c1 = fmaf(F, c1, I * G);
            float h1v = O * tanha(c1);
            if (k == 0 && writer) sh1[u] = h1v;
        }
        __syncthreads();   // BAR_A: h1(s) ready

        // ================= Phase B =================
        // one pass over sh1 feeds W_ih2@h1 (4 chains) AND W_hh1@h1 (2 chains)
        u64 r0 = zer2, r1 = zer2, r2 = zer2, r3 = zer2;
        {
            const ulonglong2* hv = (const ulonglong2*)sh1;
            #pragma unroll
            for (int j = 0; j < 6; ++j) {
                ulonglong2 ha = hv[2*j];
                ulonglong2 hb = hv[2*j + 1];
                r0 = ffma2(wi2[4*j],     ha.x, r0);
                r1 = ffma2(wi2[4*j + 1], ha.y, r1);
                r2 = ffma2(wi2[4*j + 2], hb.x, r2);
                r3 = ffma2(wi2[4*j + 3], hb.y, r3);
                a0 = ffma2(wh1[4*j],     ha.x, a0);
                a1 = ffma2(wh1[4*j + 1], ha.y, a1);
                a0 = ffma2(wh1[4*j + 2], hb.x, a0);
                a1 = ffma2(wh1[4*j + 3], hb.y, a1);
            }
            ulonglong2 hc = hv[12];
            r0 = ffma2(wi2[24], hc.x, r0);
            r1 = ffma2(wi2[25], hc.y, r1);
            a0 = ffma2(wh1[24], hc.x, a0);
            a1 = ffma2(wh1[25], hc.y, a1);
        }
        {
            u64 m = add2(add2(add2(q0, q1), add2(q2, q3)),
                         add2(add2(r0, r1), add2(r2, r3)));
            float2 mf = upk2(m);
            float g2K = mf.x + mf.y;
            float2 af = upk2(add2(a0, a1));
            a1p = af.x + af.y;                                  // K*gates1-partial(s+1)
            float v0 = fmaf(tanha(g2K), actK, actA);
            float I = __shfl_sync(0xffffffffu, v0, j0);
            float F = __shfl_sync(0xffffffffu, v0, j0 + 8);
            float G = __shfl_sync(0xffffffffu, v0, j0 + 16);
            float O = __shfl_sync(0xffffffffu, v0, j0 + 24);
            c2 = fmaf(F, c2, I * G);
            float h2v = O * tanha(c2);
            if (k == 0 && writer) sh2[u] = h2v;
            // per-warp wout.h2 partial over the 8 k==0 lanes (writer-masked)
            float py = wout_u * h2v;
            py += __shfl_xor_sync(0xffffffffu, py, 1);
            py += __shfl_xor_sync(0xffffffffu, py, 2);
            py += __shfl_xor_sync(0xffffffffu, py, 4);
            if (l == 0) ypart[w] = py;
        }
        x7_use = x7_next;          // x7(s-1) -> x7(s) for Phase A(s+1)
        x7_next = x67.y;           // x7(s+1)
        __syncthreads();   // BAR_B: h2(s), ypart(s), a1p(s+1) ready
    }

    // epilogue: y(T-1) from final ypart
    if (t == 0) {
        float y = bo;
        #pragma unroll
        for (int j = 0; j < 8; ++j) y += ypart[j];
        out[T - 1] = y;
    }
}

extern "C" void kernel_launch(void* const* d_in, const int* in_sizes, int n_in,
                              void* d_out, int out_size) {
    const int T = in_sizes[0] / INP;
    lstm_r13_kernel<<<1, NTHREADS>>>(
        (const float*)d_in[0],
        (const float*)d_in[1], (const float*)d_in[2],
        (const float*)d_in[3], (const float*)d_in[4],
        (const float*)d_in[5], (const float*)d_in[6],
        (const float*)d_in[7], (const float*)d_in[8],
        (const float*)d_in[9], (const float*)d_in[10],
        (float*)d_out, T);
}